// round 1
// baseline (speedup 1.0000x reference)
#include <cuda_runtime.h>
#include <math.h>

// C = triu(triu(A) @ triu(B)), N x N fp32, row-major.
// Tiled SGEMM exploiting triangular structure:
//  - only tiles with tileRow <= tileCol do work
//  - k loop restricted to [rowStart, colEnd) -- everything outside is zero
//  - A masked at load (zero if k < row), B masked at load (zero if k > col)
//  - output masked at store (zero if row > col)

#define BM 128
#define BN 128
#define BK 8
#define TM 8
#define TN 8

__global__ __launch_bounds__(256, 2)
void trimm_kernel(const float* __restrict__ A, const float* __restrict__ B,
                  float* __restrict__ C, int N) {
    const int bx = blockIdx.x;  // column tile
    const int by = blockIdx.y;  // row tile
    if (by > bx) return;        // strictly-lower tiles are all zero (memset handles them)

    __shared__ float As[BK][BM];
    __shared__ float Bs[BK][BN];

    const int t  = threadIdx.x;
    const int tx = t & 15;      // 0..15 -> column micro-tile
    const int ty = t >> 4;      // 0..15 -> row micro-tile

    const int rowStart = by * BM;
    const int colStart = bx * BN;

    // A loader: 128 rows x 8 k, 2 threads per row, float4 each
    const int a_row = t >> 1;        // 0..127
    const int a_k   = (t & 1) * 4;   // 0 or 4
    // B loader: 8 k x 128 cols, 32 threads per k-row, float4 each
    const int b_k   = t >> 5;        // 0..7
    const int b_col = (t & 31) * 4;  // 0..124

    float acc[TM][TN];
    #pragma unroll
    for (int i = 0; i < TM; i++)
        #pragma unroll
        for (int j = 0; j < TN; j++) acc[i][j] = 0.f;

    const int kend = colStart + BN;  // k <= col  => k < colEnd

    for (int k0 = rowStart; k0 < kend; k0 += BK) {
        // ---- load A tile (masked: zero where k < row) ----
        {
            const int grow = rowStart + a_row;
            const int gk   = k0 + a_k;
            float4 v = *reinterpret_cast<const float4*>(
                &A[(size_t)grow * N + gk]);
            if (gk + 0 < grow) v.x = 0.f;
            if (gk + 1 < grow) v.y = 0.f;
            if (gk + 2 < grow) v.z = 0.f;
            if (gk + 3 < grow) v.w = 0.f;
            As[a_k + 0][a_row] = v.x;
            As[a_k + 1][a_row] = v.y;
            As[a_k + 2][a_row] = v.z;
            As[a_k + 3][a_row] = v.w;
        }
        // ---- load B tile (masked: zero where k > col) ----
        {
            const int gk   = k0 + b_k;
            const int gcol = colStart + b_col;
            float4 v = *reinterpret_cast<const float4*>(
                &B[(size_t)gk * N + gcol]);
            if (gk > gcol + 0) v.x = 0.f;
            if (gk > gcol + 1) v.y = 0.f;
            if (gk > gcol + 2) v.z = 0.f;
            if (gk > gcol + 3) v.w = 0.f;
            *reinterpret_cast<float4*>(&Bs[b_k][b_col]) = v;
        }
        __syncthreads();

        #pragma unroll
        for (int kk = 0; kk < BK; kk++) {
            float a[TM], b[TN];
            #pragma unroll
            for (int i = 0; i < TM; i++) a[i] = As[kk][ty * TM + i];
            #pragma unroll
            for (int j = 0; j < TN; j++) b[j] = Bs[kk][tx * TN + j];
            #pragma unroll
            for (int i = 0; i < TM; i++)
                #pragma unroll
                for (int j = 0; j < TN; j++)
                    acc[i][j] = fmaf(a[i], b[j], acc[i][j]);
        }
        __syncthreads();
    }

    // ---- epilogue: mask r<=c, vectorized store ----
    #pragma unroll
    for (int i = 0; i < TM; i++) {
        const int r = rowStart + ty * TM + i;
        #pragma unroll
        for (int j = 0; j < TN; j += 4) {
            const int c = colStart + tx * TN + j;
            float4 v;
            v.x = (r <= c + 0) ? acc[i][j + 0] : 0.f;
            v.y = (r <= c + 1) ? acc[i][j + 1] : 0.f;
            v.z = (r <= c + 2) ? acc[i][j + 2] : 0.f;
            v.w = (r <= c + 3) ? acc[i][j + 3] : 0.f;
            *reinterpret_cast<float4*>(&C[(size_t)r * N + c]) = v;
        }
    }
}

extern "C" void kernel_launch(void* const* d_in, const int* in_sizes, int n_in,
                              void* d_out, int out_size) {
    const float* A = (const float*)d_in[0];
    const float* B = (const float*)d_in[1];
    float* C = (float*)d_out;

    // N from element count (N*N)
    int N = (int)(sqrt((double)in_sizes[0]) + 0.5);

    // Zero the whole output: lower triangle never written by the kernel.
    cudaMemsetAsync(d_out, 0, (size_t)out_size * sizeof(float));

    dim3 grid(N / BN, N / BM);
    dim3 block(256);
    trimm_kernel<<<grid, block>>>(A, B, C, N);
}

// round 3
// speedup vs baseline: 2.2309x; 2.2309x over previous
#include <cuda_runtime.h>
#include <cuda_bf16.h>
#include <cstdint>

// C = triu(triu(A) @ triu(B)), 4096x4096 fp32.
// Phase 1: split fp32 -> bf16 hi/lo, triangular masks baked in.
//          A -> gAhi/gAlo row-major [r][k]; B -> transposed gBthi/gBtlo [c][k].
// Phase 2: mma.sync.m16n8k16 bf16 (base sm_103 target -- no tcgen05 available),
//          3-term split product into fp32 register accumulators.
//          Tile 128x256, BK=64, cp.async double-buffered, k in [rowStart, colEnd).

#define N4K 4096

__device__ __align__(16) __nv_bfloat16 gAhi[(size_t)N4K * N4K];
__device__ __align__(16) __nv_bfloat16 gAlo[(size_t)N4K * N4K];
__device__ __align__(16) __nv_bfloat16 gBthi[(size_t)N4K * N4K];
__device__ __align__(16) __nv_bfloat16 gBtlo[(size_t)N4K * N4K];

__device__ __forceinline__ uint32_t smem_u32(const void* p) {
    uint32_t a;
    asm("{ .reg .u64 t; cvta.to.shared.u64 t, %1; cvt.u32.u64 %0, t; }" : "=r"(a) : "l"(p));
    return a;
}
#define SWZ(x) ((x) ^ (((x) >> 3) & 0x70))

__device__ __forceinline__ void ldmx4(uint32_t* r, uint32_t addr) {
    asm volatile("ldmatrix.sync.aligned.m8n8.x4.shared.b16 {%0,%1,%2,%3}, [%4];"
        : "=r"(r[0]), "=r"(r[1]), "=r"(r[2]), "=r"(r[3]) : "r"(addr));
}
__device__ __forceinline__ void mma16816(float* c, const uint32_t* a, uint32_t b0, uint32_t b1) {
    asm volatile("mma.sync.aligned.m16n8k16.row.col.f32.bf16.bf16.f32 "
        "{%0,%1,%2,%3}, {%4,%5,%6,%7}, {%8,%9}, {%0,%1,%2,%3};"
        : "+f"(c[0]), "+f"(c[1]), "+f"(c[2]), "+f"(c[3])
        : "r"(a[0]), "r"(a[1]), "r"(a[2]), "r"(a[3]), "r"(b0), "r"(b1));
}
#define CPA16(dst, src) \
    asm volatile("cp.async.cg.shared.global [%0], [%1], 16;" :: "r"(dst), "l"(src))
#define CPA_COMMIT() asm volatile("cp.async.commit_group;" ::: "memory")

// ---------------- phase 1a: split triu(A) into bf16 hi/lo ----------------
__global__ __launch_bounds__(256) void p1_split_a(const float* __restrict__ A) {
    size_t e = ((size_t)blockIdx.x * 256 + threadIdx.x) * 4;
    int r = (int)(e >> 12);
    int k = (int)(e & 4095);
    float4 v = *reinterpret_cast<const float4*>(A + e);
    if (k + 0 < r) v.x = 0.f;
    if (k + 1 < r) v.y = 0.f;
    if (k + 2 < r) v.z = 0.f;
    if (k + 3 < r) v.w = 0.f;
    __nv_bfloat16 h0 = __float2bfloat16(v.x), h1 = __float2bfloat16(v.y);
    __nv_bfloat16 h2 = __float2bfloat16(v.z), h3 = __float2bfloat16(v.w);
    __nv_bfloat16 l0 = __float2bfloat16(v.x - __bfloat162float(h0));
    __nv_bfloat16 l1 = __float2bfloat16(v.y - __bfloat162float(h1));
    __nv_bfloat16 l2 = __float2bfloat16(v.z - __bfloat162float(h2));
    __nv_bfloat16 l3 = __float2bfloat16(v.w - __bfloat162float(h3));
    __nv_bfloat162* ph = reinterpret_cast<__nv_bfloat162*>(gAhi + e);
    __nv_bfloat162* pl = reinterpret_cast<__nv_bfloat162*>(gAlo + e);
    __nv_bfloat162 a, b;
    a.x = h0; a.y = h1; b.x = h2; b.y = h3; ph[0] = a; ph[1] = b;
    a.x = l0; a.y = l1; b.x = l2; b.y = l3; pl[0] = a; pl[1] = b;
}

// ---------------- phase 1b: split+transpose triu(B): gBt[c][k] = triu(B)[k][c] ----------------
__global__ __launch_bounds__(256) void p1_split_bt(const float* __restrict__ B) {
    __shared__ __nv_bfloat16 sh[32][33];
    __shared__ __nv_bfloat16 sl[32][33];
    int c0 = blockIdx.x * 32, k0 = blockIdx.y * 32;
    int tx = threadIdx.x, ty = threadIdx.y;  // (32, 8)
    #pragma unroll
    for (int j = 0; j < 4; j++) {
        int k = k0 + ty + 8 * j, c = c0 + tx;
        float v = (k <= c) ? B[(size_t)k * N4K + c] : 0.f;
        __nv_bfloat16 h = __float2bfloat16(v);
        sh[ty + 8 * j][tx] = h;
        sl[ty + 8 * j][tx] = __float2bfloat16(v - __bfloat162float(h));
    }
    __syncthreads();
    #pragma unroll
    for (int j = 0; j < 4; j++) {
        int row = ty + 8 * j;
        size_t o = (size_t)(c0 + row) * N4K + (k0 + tx);
        gBthi[o] = sh[tx][row];
        gBtlo[o] = sl[tx][row];
    }
}

// ---------------- phase 2 ----------------
static constexpr int AHI_OFF = 0;
static constexpr int ALO_OFF = 16384;
static constexpr int BHI_OFF = 32768;
static constexpr int BLO_OFF = 65536;
static constexpr int STAGE   = 98304;           // 96KB
static constexpr int SMEM_TOTAL = 2 * STAGE;    // 192KB

__device__ __forceinline__ void load_chunk(char* smBase, int stage, int rowStart,
                                           int colStart, int k0, int tid) {
    uint32_t st = smem_u32(smBase) + stage * STAGE;
    // A hi/lo: 128 rows x 64 k = 1024 x 16B chunks each
    #pragma unroll
    for (int t = 0; t < 4; t++) {
        int e = tid + (t << 8);
        int row = e >> 3, ch = e & 7;
        size_t src = (size_t)(rowStart + row) * N4K + k0 + ch * 8;
        uint32_t d = SWZ((uint32_t)(row * 128 + ch * 16));
        CPA16(st + AHI_OFF + d, gAhi + src);
        CPA16(st + ALO_OFF + d, gAlo + src);
    }
    // B hi/lo: 256 rows x 64 k = 2048 x 16B chunks each
    #pragma unroll
    for (int t = 0; t < 8; t++) {
        int e = tid + (t << 8);
        int row = e >> 3, ch = e & 7;
        size_t src = (size_t)(colStart + row) * N4K + k0 + ch * 8;
        uint32_t d = SWZ((uint32_t)(row * 128 + ch * 16));
        CPA16(st + BHI_OFF + d, gBthi + src);
        CPA16(st + BLO_OFF + d, gBtlo + src);
    }
    CPA_COMMIT();
}

__global__ __launch_bounds__(256, 1) void trimm_mma(float* __restrict__ C) {
    extern __shared__ char sm[];
    const int tid = threadIdx.x;
    const int wid = tid >> 5, lane = tid & 31;
    const int wm = wid & 3, wn = wid >> 2;     // 4 x 2 warp grid, warp tile 32x128

    // ---- tile map: global work-descending order (w = kspan in 128-units) ----
    int bx = 15, by = 0;
    {
        int bid = blockIdx.x, cum = 0;
        #pragma unroll 1
        for (int w = 32; w >= 1; --w) {
            int bmin = (w - 1) >> 1;
            int cnt = 16 - bmin;
            if (bid < cum + cnt) { bx = bmin + (bid - cum); by = 2 * bx + 2 - w; break; }
            cum += cnt;
        }
    }
    const int rowStart = by * 128;
    const int colStart = bx * 256;
    const int nCh = ((colStart + 256) - rowStart) >> 6;   // >= 2

    float acc[128];
    #pragma unroll
    for (int i = 0; i < 128; i++) acc[i] = 0.f;

    load_chunk(sm, 0, rowStart, colStart, rowStart, tid);

    const int lrow = lane & 15;          // ldmatrix row within 16
    const int lk   = (lane >> 4) * 8;    // k-half select

    #pragma unroll 1
    for (int ci = 0; ci < nCh; ci++) {
        if (ci + 1 < nCh) {
            load_chunk(sm, (ci + 1) & 1, rowStart, colStart, rowStart + 64 * (ci + 1), tid);
            asm volatile("cp.async.wait_group 1;" ::: "memory");
        } else {
            asm volatile("cp.async.wait_group 0;" ::: "memory");
        }
        __syncthreads();

        const uint32_t st = smem_u32(sm) + (ci & 1) * STAGE;

        #pragma unroll
        for (int kk = 0; kk < 4; kk++) {
            const int krow = kk * 16;
            uint32_t ah[2][4], al[2][4];
            #pragma unroll
            for (int i = 0; i < 2; i++) {
                uint32_t off = SWZ((uint32_t)((wm * 32 + i * 16 + lrow) * 128 + (krow + lk) * 2));
                ldmx4(ah[i], st + AHI_OFF + off);
                ldmx4(al[i], st + ALO_OFF + off);
            }
            #pragma unroll
            for (int h = 0; h < 2; h++) {
                uint32_t bh0[8], bh1[8], bl0[8], bl1[8];
                #pragma unroll
                for (int j2 = 0; j2 < 4; j2++) {
                    uint32_t off = SWZ((uint32_t)((wn * 128 + h * 64 + j2 * 16 + lrow) * 128
                                                  + (krow + lk) * 2));
                    uint32_t r[4];
                    ldmx4(r, st + BHI_OFF + off);
                    bh0[2 * j2] = r[0]; bh1[2 * j2] = r[2];
                    bh0[2 * j2 + 1] = r[1]; bh1[2 * j2 + 1] = r[3];
                    ldmx4(r, st + BLO_OFF + off);
                    bl0[2 * j2] = r[0]; bl1[2 * j2] = r[2];
                    bl0[2 * j2 + 1] = r[1]; bl1[2 * j2 + 1] = r[3];
                }
                #pragma unroll
                for (int i = 0; i < 2; i++) {
                    #pragma unroll
                    for (int j = 0; j < 8; j++) {
                        float* c = &acc[(i * 16 + h * 8 + j) * 4];
                        mma16816(c, ah[i], bh0[j], bh1[j]);
                        mma16816(c, ah[i], bl0[j], bl1[j]);
                        mma16816(c, al[i], bh0[j], bh1[j]);
                    }
                }
            }
        }
        __syncthreads();
    }

    // ---- epilogue: triu-masked fp32 stores ----
    const int l4 = lane >> 2;
    const int l2 = (lane & 3) * 2;
    #pragma unroll
    for (int i = 0; i < 2; i++) {
        const int r0 = rowStart + wm * 32 + i * 16 + l4;
        const int r1 = r0 + 8;
        #pragma unroll
        for (int j = 0; j < 16; j++) {
            const int c = colStart + wn * 128 + j * 8 + l2;
            const float* a = &acc[(i * 16 + j) * 4];
            float2 v;
            v.x = (r0 <= c + 0) ? a[0] : 0.f;
            v.y = (r0 <= c + 1) ? a[1] : 0.f;
            *reinterpret_cast<float2*>(C + (size_t)r0 * N4K + c) = v;
            v.x = (r1 <= c + 0) ? a[2] : 0.f;
            v.y = (r1 <= c + 1) ? a[3] : 0.f;
            *reinterpret_cast<float2*>(C + (size_t)r1 * N4K + c) = v;
        }
    }
}

// ---------------- launch ----------------
extern "C" void kernel_launch(void* const* d_in, const int* in_sizes, int n_in,
                              void* d_out, int out_size) {
    const float* A = (const float*)d_in[0];
    const float* B = (const float*)d_in[1];
    float* C = (float*)d_out;

    cudaMemsetAsync(d_out, 0, (size_t)N4K * N4K * sizeof(float));

    p1_split_a<<<(N4K * (N4K / 4)) / 256, 256>>>(A);
    p1_split_bt<<<dim3(N4K / 32, N4K / 32), dim3(32, 8)>>>(B);

    cudaFuncSetAttribute(trimm_mma, cudaFuncAttributeMaxDynamicSharedMemorySize, SMEM_TOTAL);
    trimm_mma<<<272, 256, SMEM_TOTAL>>>(C);
}